// round 2
// baseline (speedup 1.0000x reference)
#include <cuda_runtime.h>
#include <math.h>

#define BATCH 64
#define CIN 32
#define T_IN 2048
#define FIL 64
#define WIN 5
#define T1 2044
#define T2 2040
#define LL 2036
#define DA 64
#define DD 256
#define SEC 11
#define BN_EPSF 1e-5f

#define TILE 128
#define CT 132      // conv positions per tile (TILE + WIN - 1)
#define INT_ 136    // input positions per tile
#define NTILE1 16   // tiles covering T2=2040
#define NTILE3 16   // tiles covering LL=2036
#define JP 68       // padded stride for transposed G in shared

// ---------------- scratch (device globals; no allocation allowed) ----------------
__device__ float g_h2[BATCH * FIL * T2];            // pooled conv1 output (33.4 MB)
__device__ float g_part[NTILE1 * BATCH * FIL * 2];  // per-block BN partial sum/sumsq
__device__ float g_we2[FIL * WIN];                  // BN-folded conv2 weights
__device__ float g_cterm;                           // BN-folded conv2 constant
__device__ int   g_idx[BATCH * LL];                 // bucket index per (b,l)
__device__ float g_W1T[LL * DA];                    // W1 transposed
__device__ float g_G[BATCH * DA * DD];              // bucket-aggregated W1
__device__ int   g_cnt[BATCH * DD];                 // bucket histogram
__device__ float g_A[BATCH * DD];                   // attention vector A[b,:]

// ---------------- K0: transpose W1 [DA,LL] -> [LL,DA] ----------------
extern "C" __global__ void k0_transpose(const float* __restrict__ W1) {
    int t = blockIdx.x * 256 + threadIdx.x;
    if (t < LL * DA) {
        int l = t >> 6, a = t & 63;
        g_W1T[t] = W1[a * LL + l];
    }
}

// ---------------- K1: conv1 + bias + maxpool5 + BN partial stats ----------------
extern "C" __global__ void k1_conv_pool(const float* __restrict__ x,
                                        const float* __restrict__ w1,
                                        const float* __restrict__ b1) {
    extern __shared__ float sm[];
    float* sx = sm;                        // CIN*INT_
    float* sw = sx + CIN * INT_;           // FIL*CIN*WIN
    float* sb = sw + FIL * CIN * WIN;      // FIL
    float* sc = sb + FIL;                  // FIL*CT
    float* sp = sc + FIL * CT;             // FIL*TILE

    int tile = blockIdx.x, b = blockIdx.y;
    int t0 = tile * TILE;
    int tid = threadIdx.x;
    int npool = min(TILE, T2 - t0);

    for (int i = tid; i < CIN * INT_; i += 256) {
        int c = i / INT_, p = i - c * INT_;
        int g = t0 + p;
        sx[i] = (g < T_IN) ? x[(b * CIN + c) * T_IN + g] : 0.f;
    }
    for (int i = tid; i < FIL * CIN * WIN; i += 256) sw[i] = w1[i];
    if (tid < FIL) sb[tid] = b1[tid];
    __syncthreads();

    int f = tid >> 2, q = tid & 3;
    int i0 = q * 33;                       // 4*33 = 132 conv positions
    float acc[33];
#pragma unroll
    for (int i = 0; i < 33; ++i) acc[i] = sb[f];

    const float* swf = sw + f * (CIN * WIN);
    for (int c = 0; c < CIN; ++c) {
        float w0 = swf[c * 5 + 0], wa = swf[c * 5 + 1], wb = swf[c * 5 + 2],
              wc = swf[c * 5 + 3], wd = swf[c * 5 + 4];
        const float* xr = sx + c * INT_ + i0;
        float x0 = xr[0], x1 = xr[1], x2 = xr[2], x3 = xr[3];
#pragma unroll
        for (int i = 0; i < 33; ++i) {
            float x4 = xr[i + 4];
            acc[i] += w0 * x0 + wa * x1 + wb * x2 + wc * x3 + wd * x4;
            x0 = x1; x1 = x2; x2 = x3; x3 = x4;
        }
    }
#pragma unroll
    for (int i = 0; i < 33; ++i) sc[f * CT + i0 + i] = acc[i];
    __syncthreads();

    // maxpool window 5 stride 1 + per-channel partial stats
    float ls = 0.f, ls2 = 0.f;
    int p0 = q * 32;
    int pe = min(npool, p0 + 32);
    for (int p = p0; p < pe; ++p) {
        const float* cr = sc + f * CT + p;
        float m = cr[0];
        m = fmaxf(m, cr[1]); m = fmaxf(m, cr[2]);
        m = fmaxf(m, cr[3]); m = fmaxf(m, cr[4]);
        sp[f * TILE + p] = m;
        ls += m; ls2 += m * m;
    }
    ls  += __shfl_xor_sync(0xffffffffu, ls, 1);
    ls  += __shfl_xor_sync(0xffffffffu, ls, 2);
    ls2 += __shfl_xor_sync(0xffffffffu, ls2, 1);
    ls2 += __shfl_xor_sync(0xffffffffu, ls2, 2);
    if (q == 0) {
        int blk = b * NTILE1 + tile;
        g_part[(blk * FIL + f) * 2 + 0] = ls;
        g_part[(blk * FIL + f) * 2 + 1] = ls2;
    }
    __syncthreads();

    for (int o = tid; o < FIL * npool; o += 256) {
        int ff = o / npool, p = o - ff * npool;
        g_h2[(b * FIL + ff) * T2 + t0 + p] = sp[ff * TILE + p];
    }
}

// ---------------- K2: reduce BN stats, fold into conv2 weights ----------------
extern "C" __global__ void k2_stats(const float* __restrict__ w2,
                                    const float* __restrict__ b2,
                                    const float* __restrict__ gamma,
                                    const float* __restrict__ beta) {
    __shared__ float sct[FIL];
    int f = threadIdx.x;  // blockDim = 64
    double s = 0.0, s2 = 0.0;
    for (int blk = 0; blk < NTILE1 * BATCH; ++blk) {
        s  += (double)g_part[(blk * FIL + f) * 2 + 0];
        s2 += (double)g_part[(blk * FIL + f) * 2 + 1];
    }
    double N = (double)BATCH * (double)T2;
    double mud = s / N;
    float mu = (float)mud;
    float var = (float)(s2 / N - mud * mud);
    float scale = gamma[f] * rsqrtf(var + BN_EPSF);
    float shift = beta[f] - mu * scale;
    float wsum = 0.f;
    for (int k = 0; k < WIN; ++k) {
        float wv = w2[f * WIN + k];
        g_we2[f * WIN + k] = wv * scale;
        wsum += wv;
    }
    sct[f] = shift * wsum;
    __syncthreads();
    if (f == 0) {
        float c = b2[0];
        for (int i = 0; i < FIL; ++i) c += sct[i];
        g_cterm = c;
    }
}

// ---------------- K3: conv2 (BN folded) + relu + sigmoid + bucket index ----------------
extern "C" __global__ void k3_conv2_idx() {
    __shared__ float sh[FIL * CT];
    __shared__ float swe[FIL * WIN];
    __shared__ float sct;
    int tile = blockIdx.x, b = blockIdx.y;
    int t0 = tile * TILE;
    int tid = threadIdx.x;  // 128
    for (int o = tid; o < FIL * CT; o += 128) {
        int f = o / CT, i = o - f * CT;
        int g = t0 + i;
        sh[o] = (g < T2) ? g_h2[(b * FIL + f) * T2 + g] : 0.f;
    }
    for (int o = tid; o < FIL * WIN; o += 128) swe[o] = g_we2[o];
    if (tid == 0) sct = g_cterm;
    __syncthreads();

    int l = t0 + tid;
    if (l < LL) {
        float z = sct;
#pragma unroll 8
        for (int f = 0; f < FIL; ++f) {
            const float* hr = sh + f * CT + tid;
            const float* wr = swe + f * WIN;
            z += wr[0] * hr[0] + wr[1] * hr[1] + wr[2] * hr[2]
               + wr[3] * hr[3] + wr[4] * hr[4];
        }
        z = fmaxf(z, 0.f);
        float c = 1.f / (1.f + expf(-z));
        int iv = (int)ceilf(c * 256.f) - 1;
        iv = max(0, min(255, iv));
        g_idx[b * LL + l] = iv;
    }
}

// ---------------- K4: bucket scatter G[b,a,j] + histogram ----------------
extern "C" __global__ void k4_scatter() {
    extern __shared__ float sm4[];
    float* sG = sm4;                          // DA*257 (bank-conflict-free)
    int* shist = (int*)(sG + DA * 257);       // DD
    int b = blockIdx.x;
    int tid = threadIdx.x;  // 256
    for (int o = tid; o < DA * 257; o += 256) sG[o] = 0.f;
    for (int o = tid; o < DD; o += 256) shist[o] = 0;
    __syncthreads();

    int a = tid & 63, q = tid >> 6;
    int l0 = q * 509, l1 = l0 + 509;          // 4*509 = 2036 exactly
    for (int l = l0; l < l1; ++l) {
        int j = g_idx[b * LL + l];
        float w = g_W1T[l * DA + a];
        atomicAdd(&sG[a * 257 + j], w);
        if (a == 0) atomicAdd(&shist[j], 1);
    }
    __syncthreads();

    for (int o = tid; o < DA * DD; o += 256)
        g_G[b * DA * DD + o] = sG[(o >> 8) * 257 + (o & 255)];
    for (int o = tid; o < DD; o += 256)
        g_cnt[b * DD + o] = shist[o];
}

// ---------------- K5: t = tanh(G @ emb256); A = W2^T t  ----------------
extern "C" __global__ void k5_gemm(const float* __restrict__ emb,
                                   const float* __restrict__ W2) {
    extern __shared__ float sm5[];
    float* sGT = sm5;                  // DD*JP  (G transposed, padded)
    float* sA  = sGT + DD * JP;        // 128
    float* sW2 = sA + 128;             // 64
    int b = blockIdx.x, half = blockIdx.y;
    int tid = threadIdx.x;  // 128

    for (int o = tid; o < DA * DD; o += 128) {
        int a = o >> 8, j = o & 255;
        sGT[j * JP + a] = g_G[b * DA * DD + o];
    }
    sA[tid] = 0.f;
    if (tid < DA) sW2[tid] = W2[tid];
    __syncthreads();

    int ta = tid >> 4, td = tid & 15;       // 8 x 16 thread grid
    int a0 = ta * 8;
    int d0 = half * 128 + td * 8;
    float acc[8][8];
#pragma unroll
    for (int r = 0; r < 8; ++r)
#pragma unroll
        for (int s = 0; s < 8; ++s) acc[r][s] = 0.f;

    const float* embd = emb + d0;
#pragma unroll 2
    for (int j = 0; j < DD; ++j) {
        float4 ga = *(const float4*)&sGT[j * JP + a0];
        float4 gb = *(const float4*)&sGT[j * JP + a0 + 4];
        float4 e0 = *(const float4*)&embd[j * DD];
        float4 e1 = *(const float4*)&embd[j * DD + 4];
        float gv[8] = {ga.x, ga.y, ga.z, ga.w, gb.x, gb.y, gb.z, gb.w};
        float ev[8] = {e0.x, e0.y, e0.z, e0.w, e1.x, e1.y, e1.z, e1.w};
#pragma unroll
        for (int r = 0; r < 8; ++r)
#pragma unroll
            for (int s = 0; s < 8; ++s)
                acc[r][s] += gv[r] * ev[s];
    }

    float pA[8];
#pragma unroll
    for (int s = 0; s < 8; ++s) pA[s] = 0.f;
#pragma unroll
    for (int r = 0; r < 8; ++r) {
        float w = sW2[a0 + r];
#pragma unroll
        for (int s = 0; s < 8; ++s)
            pA[s] += w * tanhf(acc[r][s]);
    }
#pragma unroll
    for (int s = 0; s < 8; ++s)
        atomicAdd(&sA[td * 8 + s], pA[s]);
    __syncthreads();
    g_A[b * DD + half * 128 + tid] = sA[tid];
}

// ---------------- K6: bucket softmax + att gather + scores ----------------
extern "C" __global__ void k6_final(const float* __restrict__ emb,
                                    const float* __restrict__ lin_w,
                                    const float* __restrict__ lin_b,
                                    float* __restrict__ out) {
    __shared__ float sA[DD];
    __shared__ float sE[DD];
    __shared__ float red[256];
    int b = blockIdx.x;
    int tid = threadIdx.x;  // 256
    sA[tid] = g_A[b * DD + tid];
    __syncthreads();

    int j = tid;
    float P = 0.f;
    const float4* er = (const float4*)(emb + (size_t)j * DD);
#pragma unroll 8
    for (int d4 = 0; d4 < DD / 4; ++d4) {
        float4 e = er[d4];
        P += e.x * sA[d4 * 4 + 0] + e.y * sA[d4 * 4 + 1]
           + e.z * sA[d4 * 4 + 2] + e.w * sA[d4 * 4 + 3];
    }
    int cj = g_cnt[b * DD + j];
    red[tid] = (cj > 0) ? P : -3.0e38f;
    __syncthreads();
    for (int st = 128; st > 0; st >>= 1) {
        if (tid < st) red[tid] = fmaxf(red[tid], red[tid + st]);
        __syncthreads();
    }
    float m = red[0];
    __syncthreads();
    float ex = (cj > 0) ? expf(P - m) : 0.f;
    red[tid] = (float)cj * ex;
    __syncthreads();
    for (int st = 128; st > 0; st >>= 1) {
        if (tid < st) red[tid] += red[tid + st];
        __syncthreads();
    }
    float Z = red[0];
    sE[j] = ex / Z;
    __syncthreads();

    for (int l = tid; l < LL; l += 256)
        out[b * LL + l] = sE[g_idx[b * LL + l]];

    if (tid < SEC) {
        float s = lin_b[tid];
        const float* wr = lin_w + tid * DD;
        for (int d = 0; d < DD; ++d) s += wr[d] * sA[d];
        out[BATCH * LL + b * SEC + tid] = s;
    }
}

// ---------------- launch ----------------
extern "C" void kernel_launch(void* const* d_in, const int* in_sizes, int n_in,
                              void* d_out, int out_size) {
    const float* x     = (const float*)d_in[0];
    const float* c1w   = (const float*)d_in[1];
    const float* c1b   = (const float*)d_in[2];
    const float* gamma = (const float*)d_in[3];
    const float* beta  = (const float*)d_in[4];
    const float* c2w   = (const float*)d_in[5];
    const float* c2b   = (const float*)d_in[6];
    const float* emb   = (const float*)d_in[7];
    const float* W1    = (const float*)d_in[8];
    const float* W2    = (const float*)d_in[9];
    const float* lw    = (const float*)d_in[10];
    const float* lb    = (const float*)d_in[11];
    float* out = (float*)d_out;

    size_t sm1 = (size_t)(CIN * INT_ + FIL * CIN * WIN + FIL + FIL * CT + FIL * TILE) * sizeof(float);
    size_t sm4 = (size_t)DA * 257 * sizeof(float) + (size_t)DD * sizeof(int);
    size_t sm5 = (size_t)(DD * JP + 128 + DA) * sizeof(float);
    cudaFuncSetAttribute(k1_conv_pool, cudaFuncAttributeMaxDynamicSharedMemorySize, (int)sm1);
    cudaFuncSetAttribute(k4_scatter,   cudaFuncAttributeMaxDynamicSharedMemorySize, (int)sm4);
    cudaFuncSetAttribute(k5_gemm,      cudaFuncAttributeMaxDynamicSharedMemorySize, (int)sm5);

    k0_transpose<<<(LL * DA + 255) / 256, 256>>>(W1);
    k1_conv_pool<<<dim3(NTILE1, BATCH), 256, sm1>>>(x, c1w, c1b);
    k2_stats<<<1, FIL>>>(c2w, c2b, gamma, beta);
    k3_conv2_idx<<<dim3(NTILE3, BATCH), 128>>>();
    k4_scatter<<<BATCH, 256, sm4>>>();
    k5_gemm<<<dim3(BATCH, 2), 128, sm5>>>(emb, W2);
    k6_final<<<BATCH, 256>>>(emb, lw, lb, out);
}

// round 7
// speedup vs baseline: 1.6838x; 1.6838x over previous
#include <cuda_runtime.h>
#include <math.h>

#define BATCH 64
#define CIN 32
#define T_IN 2048
#define FIL 64
#define WIN 5
#define T1 2044
#define T2 2040
#define LL 2036
#define DA 64
#define DD 256
#define SEC 11
#define BN_EPSF 1e-5f

#define TILE 128        // pooled outputs per k1 block
#define INT_ 136        // input positions per k1 tile
#define NTILE1 16       // k1 tiles over T2
#define TILE3 256       // l positions per k3 block
#define NTILE3 8        // k3 tiles over LL
#define JP 68           // padded a-stride for sGT in k5

// ---------------- scratch (device globals) ----------------
__device__ float g_h2[BATCH * T2 * FIL];            // pooled conv1 out, [b][t][f]
__device__ float g_part[NTILE1 * BATCH * FIL * 2];  // per-block BN partials
__device__ float g_we2[FIL * WIN];
__device__ float g_cterm;
__device__ int   g_idx[BATCH * LL];
__device__ float g_W1T[LL * DA];                    // W1 transposed [l][a]
__device__ float g_w1T[CIN * WIN * FIL];            // conv1 w transposed [c][k][f]
__device__ float g_Gc[BATCH * DD * DA];             // compact G [b][jj][a]
__device__ int   g_jlist[BATCH * DD];
__device__ int   g_nact[BATCH];
__device__ int   g_cnt[BATCH * DD];
__device__ float g_A[BATCH * DD];

// ---------------- K0: transposes ----------------
extern "C" __global__ void k0_prep(const float* __restrict__ W1,
                                   const float* __restrict__ w1) {
    int t = blockIdx.x * 256 + threadIdx.x;
    if (t < LL * DA) {
        int l = t >> 6, a = t & 63;
        g_W1T[t] = W1[a * LL + l];
    }
    int u = t - LL * DA;
    if (u >= 0 && u < CIN * WIN * FIL) {
        int f = u & 63, ck = u >> 6;          // ck = c*5+k
        g_w1T[u] = w1[f * (CIN * WIN) + ck];
    }
}

// ---------------- K1: conv1 + maxpool5 + BN partials (register pooling) -------
// 256 threads = 8 warps. warp w: q = w>>1 (position quarter), fhi = w&1.
// thread filter f = fhi*32 + lane; computes conv positions 32q .. 32q+35,
// pools to 32 outputs. x LDS is warp-uniform (broadcast, conflict-free).
// NOTE: inner expression kept IDENTICAL to the validated R1 kernel —
// idx = ceil(sigmoid(z)*256)-1 downstream is a discontinuity amplified by
// saturated tanh; changing FFMA contraction order flips buckets vs reference.
extern "C" __global__ void __launch_bounds__(256, 3)
k1_conv_pool(const float* __restrict__ x, const float* __restrict__ b1) {
    extern __shared__ float sm[];
    float* sx  = sm;                    // CIN*INT_  (4352)
    float* sp  = sx + CIN * INT_;       // TILE*FIL  (8192) layout [p][f]
    float* sst = sp + TILE * FIL;       // 8*32*2    (512)

    int tile = blockIdx.x, b = blockIdx.y;
    int t0 = tile * TILE;
    int tid = threadIdx.x;
    int w = tid >> 5, lane = tid & 31;
    int q = w >> 1, fhi = w & 1;
    int f = fhi * 32 + lane;
    int npool = min(TILE, T2 - t0);

    for (int i = tid; i < CIN * INT_; i += 256) {
        int c = i / INT_, p = i - c * INT_;
        int g = t0 + p;
        sx[i] = (g < T_IN) ? x[(b * CIN + c) * T_IN + g] : 0.f;
    }
    __syncthreads();

    float acc[36];
    float bias = __ldg(&b1[f]);
#pragma unroll
    for (int i = 0; i < 36; ++i) acc[i] = bias;

    int base = q * 32;
    for (int c = 0; c < CIN; ++c) {
        const float* wr = g_w1T + c * WIN * FIL + f;
        float w0 = __ldg(wr), wa = __ldg(wr + FIL), wb = __ldg(wr + 2 * FIL),
              wc = __ldg(wr + 3 * FIL), wd = __ldg(wr + 4 * FIL);
        const float* xr = sx + c * INT_ + base;
        float x0 = xr[0], x1 = xr[1], x2 = xr[2], x3 = xr[3];
#pragma unroll
        for (int i = 0; i < 36; ++i) {
            float x4 = xr[i + 4];
            acc[i] += w0 * x0 + wa * x1 + wb * x2 + wc * x3 + wd * x4;
            x0 = x1; x1 = x2; x2 = x3; x3 = x4;
        }
    }

    // pool + stats in registers (max is exact; order-insensitive)
    float ls = 0.f, ls2 = 0.f;
#pragma unroll
    for (int i = 0; i < 32; ++i) {
        float m = acc[i];
        m = fmaxf(m, acc[i + 1]); m = fmaxf(m, acc[i + 2]);
        m = fmaxf(m, acc[i + 3]); m = fmaxf(m, acc[i + 4]);
        int p = base + i;
        sp[p * FIL + f] = m;                 // lanes consecutive -> no conflict
        if (p < npool) { ls += m; ls2 += m * m; }
    }
    sst[(w * 32 + lane) * 2 + 0] = ls;
    sst[(w * 32 + lane) * 2 + 1] = ls2;
    __syncthreads();

    if (tid < FIL) {
        int fh = tid >> 5, ln = tid & 31;
        float s = 0.f, s2 = 0.f;
        for (int qq = 0; qq < 4; ++qq) {
            int ww = qq * 2 + fh;
            s  += sst[(ww * 32 + ln) * 2 + 0];
            s2 += sst[(ww * 32 + ln) * 2 + 1];
        }
        int blk = b * NTILE1 + tile;
        g_part[(blk * FIL + tid) * 2 + 0] = s;
        g_part[(blk * FIL + tid) * 2 + 1] = s2;
    }

    for (int o = tid; o < FIL * TILE; o += 256) {
        int p = o >> 6;
        if (p < npool)
            g_h2[((size_t)b * T2 + t0 + p) * FIL + (o & 63)] = sp[o];
    }
}

// ---------------- K2: reduce BN stats, fold into conv2 ----------------
extern "C" __global__ void k2_stats(const float* __restrict__ w2,
                                    const float* __restrict__ b2,
                                    const float* __restrict__ gamma,
                                    const float* __restrict__ beta) {
    __shared__ double ssum[256], ssum2[256];
    __shared__ float sct[FIL];
    int tid = threadIdx.x;  // 256
    int f = tid & 63, seg = tid >> 6;
    double s = 0.0, s2 = 0.0;
    for (int blk = seg; blk < NTILE1 * BATCH; blk += 4) {
        s  += (double)g_part[(blk * FIL + f) * 2 + 0];
        s2 += (double)g_part[(blk * FIL + f) * 2 + 1];
    }
    ssum[tid] = s; ssum2[tid] = s2;
    __syncthreads();
    if (seg == 0) {
        for (int k = 1; k < 4; ++k) { s += ssum[f + 64 * k]; s2 += ssum2[f + 64 * k]; }
        double N = (double)BATCH * (double)T2;
        double mud = s / N;
        float mu = (float)mud;
        float var = (float)(s2 / N - mud * mud);
        float scale = gamma[f] * rsqrtf(var + BN_EPSF);
        float shift = beta[f] - mu * scale;
        float wsum = 0.f;
        for (int k = 0; k < WIN; ++k) {
            float wv = w2[f * WIN + k];
            g_we2[f * WIN + k] = wv * scale;
            wsum += wv;
        }
        sct[f] = shift * wsum;
    }
    __syncthreads();
    if (tid == 0) {
        float c = b2[0];
        for (int i = 0; i < FIL; ++i) c += sct[i];
        g_cterm = c;
    }
}

// ---------------- K3: conv2 (BN folded) + relu + sigmoid + bucket index ------
// f-outer loop with the R1 expression form (rounding-identical to the
// validated kernel); shared layout [t][f] stride-65 is conflict-free.
extern "C" __global__ void k3_conv2_idx() {
    extern __shared__ float sm3[];
    float* sh  = sm3;                     // (TILE3+4)*65  layout [t][f] pad
    float* swe = sh + (TILE3 + 4) * 65;   // FIL*WIN
    __shared__ float sct;
    int tile = blockIdx.x, b = blockIdx.y;
    int t0 = tile * TILE3;
    int tid = threadIdx.x;  // 256

    for (int o = tid; o < (TILE3 + 4) * FIL; o += 256) {
        int tl = o >> 6, ff = o & 63;
        int t = t0 + tl;
        sh[tl * 65 + ff] = (t < T2) ? g_h2[((size_t)b * T2 + t) * FIL + ff] : 0.f;
    }
    for (int o = tid; o < FIL * WIN; o += 256) swe[o] = g_we2[o];
    if (tid == 0) sct = g_cterm;
    __syncthreads();

    int l = t0 + tid;
    if (l < LL) {
        float z = sct;
#pragma unroll 8
        for (int f = 0; f < FIL; ++f) {
            const float* hr = sh + tid * 65 + f;   // h[t=tid+k][f] at hr + 65k
            const float* wr = swe + f * WIN;
            z += wr[0] * hr[0] + wr[1] * hr[65] + wr[2] * hr[130]
               + wr[3] * hr[195] + wr[4] * hr[260];
        }
        z = fmaxf(z, 0.f);
        float c = 1.f / (1.f + expf(-z));
        int iv = (int)ceilf(c * 256.f) - 1;
        iv = max(0, min(255, iv));
        g_idx[b * LL + l] = iv;
    }
}

// ---------------- K4: run-length bucket scatter + compaction ----------------
extern "C" __global__ void k4_scatter() {
    extern __shared__ float sm4[];
    float* sG   = sm4;                         // DA*257
    int* shist  = (int*)(sG + DA * 257);       // 256
    int* sscan  = shist + 256;                 // 256
    int* spos   = sscan + 256;                 // 256
    int b = blockIdx.x;
    int tid = threadIdx.x;  // 256
    for (int o = tid; o < DA * 257; o += 256) sG[o] = 0.f;
    shist[tid] = 0;
    __syncthreads();

    int a = tid & 63, q = tid >> 6;
    int l0 = q * 509, l1 = l0 + 509;           // 4*509 = 2036
    int jprev = -1, cacc = 0;
    float wacc = 0.f;
    for (int l = l0; l < l1; ++l) {
        int j = g_idx[b * LL + l];
        float wv = g_W1T[l * DA + a];
        if (j != jprev) {
            if (jprev >= 0) {
                atomicAdd(&sG[a * 257 + jprev], wacc);
                if (a == 0) atomicAdd(&shist[jprev], cacc);
            }
            jprev = j; wacc = wv; cacc = 1;
        } else { wacc += wv; ++cacc; }
    }
    if (jprev >= 0) {
        atomicAdd(&sG[a * 257 + jprev], wacc);
        if (a == 0) atomicAdd(&shist[jprev], cacc);
    }
    __syncthreads();

    // compact: prefix-sum of occupancy flags
    int cflag = (shist[tid] > 0) ? 1 : 0;
    sscan[tid] = cflag;
    __syncthreads();
    for (int off = 1; off < 256; off <<= 1) {
        int add = (tid >= off) ? sscan[tid - off] : 0;
        __syncthreads();
        sscan[tid] += add;
        __syncthreads();
    }
    int pos = sscan[tid] - cflag;
    spos[tid] = pos;
    if (cflag) g_jlist[b * DD + pos] = tid;
    if (tid == 255) g_nact[b] = sscan[255];
    g_cnt[b * DD + tid] = shist[tid];
    __syncthreads();

    for (int o = tid; o < DD * DA; o += 256) {
        int j = o >> 6, aa = o & 63;
        if (shist[j] > 0)
            g_Gc[((size_t)b * DD + spos[j]) * DA + aa] = sG[aa * 257 + j];
    }
}

// ---------------- K5: t = tanh(Gc @ emb_active); A = W2^T t ----------------
extern "C" __global__ void k5_gemm(const float* __restrict__ emb,
                                   const float* __restrict__ W2) {
    extern __shared__ float sm5[];
    float* sGT = sm5;                   // DD*JP (only nact rows used)
    float* sA  = sGT + DD * JP;         // 128
    float* sW2 = sA + 128;              // 64
    int*   sjl = (int*)(sW2 + DA);      // 256
    int b = blockIdx.x, half = blockIdx.y;
    int tid = threadIdx.x;  // 128

    int nact = g_nact[b];
    for (int o = tid; o < nact * DA; o += 128) {
        int jj = o >> 6, a = o & 63;
        sGT[jj * JP + a] = g_Gc[((size_t)b * DD + jj) * DA + a];
    }
    for (int o = tid; o < DD; o += 128) sjl[o] = g_jlist[b * DD + o];
    sA[tid] = 0.f;
    if (tid < DA) sW2[tid] = W2[tid];
    __syncthreads();

    int ta = tid >> 4, td = tid & 15;   // 8 x 16
    int a0 = ta * 8;
    int d0 = half * 128 + td * 8;
    float acc[8][8];
#pragma unroll
    for (int r = 0; r < 8; ++r)
#pragma unroll
        for (int s = 0; s < 8; ++s) acc[r][s] = 0.f;

    for (int jj = 0; jj < nact; ++jj) {
        const float* er = emb + (size_t)sjl[jj] * DD + d0;
        float4 ga = *(const float4*)&sGT[jj * JP + a0];
        float4 gb = *(const float4*)&sGT[jj * JP + a0 + 4];
        float4 e0 = __ldg((const float4*)er);
        float4 e1 = __ldg((const float4*)(er + 4));
        float gv[8] = {ga.x, ga.y, ga.z, ga.w, gb.x, gb.y, gb.z, gb.w};
        float ev[8] = {e0.x, e0.y, e0.z, e0.w, e1.x, e1.y, e1.z, e1.w};
#pragma unroll
        for (int r = 0; r < 8; ++r)
#pragma unroll
            for (int s = 0; s < 8; ++s)
                acc[r][s] = fmaf(gv[r], ev[s], acc[r][s]);
    }

    float pA[8];
#pragma unroll
    for (int s = 0; s < 8; ++s) pA[s] = 0.f;
#pragma unroll
    for (int r = 0; r < 8; ++r) {
        float wv = sW2[a0 + r];
#pragma unroll
        for (int s = 0; s < 8; ++s)
            pA[s] = fmaf(wv, tanhf(acc[r][s]), pA[s]);
    }
#pragma unroll
    for (int s = 0; s < 8; ++s)
        atomicAdd(&sA[td * 8 + s], pA[s]);
    __syncthreads();
    g_A[b * DD + half * 128 + tid] = sA[tid];
}

// ---------------- K6: bucket softmax + att gather + scores ----------------
extern "C" __global__ void k6_final(const float* __restrict__ emb,
                                    const float* __restrict__ lin_w,
                                    const float* __restrict__ lin_b,
                                    float* __restrict__ out) {
    __shared__ float sA[DD];
    __shared__ float sE[DD];
    __shared__ float red[256];
    int b = blockIdx.x;
    int tid = threadIdx.x;  // 256
    sA[tid] = g_A[b * DD + tid];
    __syncthreads();

    int j = tid;
    float P = 0.f;
    const float4* er = (const float4*)(emb + (size_t)j * DD);
#pragma unroll 8
    for (int d4 = 0; d4 < DD / 4; ++d4) {
        float4 e = __ldg(er + d4);
        P += e.x * sA[d4 * 4 + 0] + e.y * sA[d4 * 4 + 1]
           + e.z * sA[d4 * 4 + 2] + e.w * sA[d4 * 4 + 3];
    }
    int cj = g_cnt[b * DD + j];
    red[tid] = (cj > 0) ? P : -3.0e38f;
    __syncthreads();
    for (int st = 128; st > 0; st >>= 1) {
        if (tid < st) red[tid] = fmaxf(red[tid], red[tid + st]);
        __syncthreads();
    }
    float m = red[0];
    __syncthreads();
    float ex = (cj > 0) ? expf(P - m) : 0.f;
    red[tid] = (float)cj * ex;
    __syncthreads();
    for (int st = 128; st > 0; st >>= 1) {
        if (tid < st) red[tid] += red[tid + st];
        __syncthreads();
    }
    float Z = red[0];
    sE[j] = ex / Z;
    __syncthreads();

    for (int l = tid; l < LL; l += 256)
        out[b * LL + l] = sE[g_idx[b * LL + l]];

    if (tid < SEC) {
        float s = lin_b[tid];
        const float* wr = lin_w + tid * DD;
        for (int d = 0; d < DD; ++d) s += wr[d] * sA[d];
        out[BATCH * LL + b * SEC + tid] = s;
    }
}

// ---------------- launch ----------------
extern "C" void kernel_launch(void* const* d_in, const int* in_sizes, int n_in,
                              void* d_out, int out_size) {
    const float* x     = (const float*)d_in[0];
    const float* c1w   = (const float*)d_in[1];
    const float* c1b   = (const float*)d_in[2];
    const float* gamma = (const float*)d_in[3];
    const float* beta  = (const float*)d_in[4];
    const float* c2w   = (const float*)d_in[5];
    const float* c2b   = (const float*)d_in[6];
    const float* emb   = (const float*)d_in[7];
    const float* W1    = (const float*)d_in[8];
    const float* W2    = (const float*)d_in[9];
    const float* lw    = (const float*)d_in[10];
    const float* lb    = (const float*)d_in[11];
    float* out = (float*)d_out;

    size_t sm1 = (size_t)(CIN * INT_ + TILE * FIL + 8 * 32 * 2) * sizeof(float);
    size_t sm3 = (size_t)((TILE3 + 4) * 65 + FIL * WIN) * sizeof(float);
    size_t sm4 = (size_t)DA * 257 * sizeof(float) + 3 * 256 * sizeof(int);
    size_t sm5 = (size_t)(DD * JP + 128 + DA) * sizeof(float) + DD * sizeof(int);
    cudaFuncSetAttribute(k1_conv_pool, cudaFuncAttributeMaxDynamicSharedMemorySize, (int)sm1);
    cudaFuncSetAttribute(k3_conv2_idx, cudaFuncAttributeMaxDynamicSharedMemorySize, (int)sm3);
    cudaFuncSetAttribute(k4_scatter,   cudaFuncAttributeMaxDynamicSharedMemorySize, (int)sm4);
    cudaFuncSetAttribute(k5_gemm,      cudaFuncAttributeMaxDynamicSharedMemorySize, (int)sm5);

    int n0 = LL * DA + CIN * WIN * FIL;
    k0_prep<<<(n0 + 255) / 256, 256>>>(W1, c1w);
    k1_conv_pool<<<dim3(NTILE1, BATCH), 256, sm1>>>(x, c1b);
    k2_stats<<<1, 256>>>(c2w, c2b, gamma, beta);
    k3_conv2_idx<<<dim3(NTILE3, BATCH), 256, sm3>>>();
    k4_scatter<<<BATCH, 256, sm4>>>();
    k5_gemm<<<dim3(BATCH, 2), 128, sm5>>>(emb, W2);
    k6_final<<<BATCH, 256>>>(emb, lw, lb, out);
}